// round 7
// baseline (speedup 1.0000x reference)
#include <cuda_runtime.h>
#include <cuda_bf16.h>

// ---------------------------------------------------------------------------
// 2-layer GCN + linear classifier, using linearity of the aggregation:
//   Agg(x@W) == Agg(x)@W, so each layer is  h = relu(Agg(t) @ W + b).
//   k1: h1  = relu(Agg(x)  @ W1 + b1)
//   k2: out = relu(Agg(h1) @ W2 + b2) @ Wc + bc
// Agg(t)[n] = t[n]*inv[n]^2 + sum_{e: dst=n} t[src_e]*inv[src_e]*inv[n]
// inv[i] = rsqrt(1 + indeg[i])                (self-loops included)
//
// R6: gemm1 deleted via Agg/W commutation; CSR build collapsed to 3 kernels
//     (inline is64 detect, single-block full scan with deg reset for graph
//     replay); half-warp float4 gather (2 edges per LDG.128). 9 -> 5 launches.
// ---------------------------------------------------------------------------

#define MAXN 50176
#define MAXE 1200000
#define DIN 64

__device__ int   g_deg[MAXN];        // statically zero; reset to 0 each run
__device__ float g_inv[MAXN];
__device__ int   g_off[MAXN + 1];
__device__ int   g_cur[MAXN];
__device__ int2  g_edge[MAXE];       // {src, float-bits weight}
__device__ float g_B[MAXN * DIN];

// --------------------------- index width handling --------------------------
// If the edge buffer is int64 (values < 2^31), every odd 32-bit word is 0.
// Each warp detects this locally from the first 256 words (deterministic).

__device__ __forceinline__ int detect64(const int* __restrict__ w) {
    int lane = threadIdx.x & 31;
    int bad = 0;
    #pragma unroll
    for (int j = 0; j < 4; j++)
        if (w[1 + 2 * (lane * 4 + j)] != 0) bad = 1;
    return (__ballot_sync(0xffffffffu, bad) == 0u);
}

__device__ __forceinline__ int load_idx(const int* p, long i, int is64) {
    if (is64) return (int)((const long long*)p)[i];
    return p[i];
}

// ------------------------------- CSR build ---------------------------------

__global__ void count_deg_k(const int* __restrict__ ei, int E) {
    int is64 = detect64(ei);
    int e = blockIdx.x * blockDim.x + threadIdx.x;
    if (e >= E) return;
    int d = load_idx(ei, (long)E + e, is64);
    atomicAdd(&g_deg[d], 1);
}

// Single block does the whole exclusive scan: offsets[n+1], inv, cur,
// and resets g_deg to zero so the next graph replay starts clean.
__global__ __launch_bounds__(1024) void scan_all_k(int n) {
    __shared__ int s[1024];
    const int C = (n + 1023) >> 10;          // elems per thread
    int t = threadIdx.x;
    int i0 = t * C;
    int i1 = i0 + C; if (i1 > n) i1 = n;

    int sum = 0;
    for (int i = i0; i < i1; i++) {
        int c = g_deg[i];
        g_inv[i] = rsqrtf((float)(c + 1));
        sum += c;
    }
    s[t] = sum;
    __syncthreads();
    #pragma unroll
    for (int d = 1; d < 1024; d <<= 1) {
        int v = (t >= d) ? s[t - d] : 0;
        __syncthreads();
        s[t] += v;
        __syncthreads();
    }
    int run = s[t] - sum;                    // exclusive prefix
    for (int i = i0; i < i1; i++) {
        int c = g_deg[i];
        g_off[i] = run;
        g_cur[i] = run;
        run += c;
        g_deg[i] = 0;                        // reset for next replay
    }
    if (t == 1023) g_off[n] = s[1023];
}

__global__ void scatter_k(const int* __restrict__ ei, int E) {
    int is64 = detect64(ei);
    int e = blockIdx.x * blockDim.x + threadIdx.x;
    if (e >= E) return;
    int sN = load_idx(ei, e, is64);
    int d  = load_idx(ei, (long)E + e, is64);
    int pos = atomicAdd(&g_cur[d], 1);
    g_edge[pos] = make_int2(sN, __float_as_int(g_inv[sN] * g_inv[d]));
}

// ---------------------- aggregation + fused transform -----------------------
// One warp per node. Gather: half-warp owns a full 64-float row as float4
// (lane = 16*half + fl; fl indexes 4-float chunk) -> 2 edges per LDG.128.
// Epilogue: h = relu(Agg_row @ W + b); STAGE 2 additionally applies the
// 64x16 classifier and writes 16 outputs.

template <int STAGE>
__global__ __launch_bounds__(256) void agg_mm_k(
    const float* __restrict__ T, const float* __restrict__ Wg,
    const float* __restrict__ bg, const float* __restrict__ Wcg,
    const float* __restrict__ bcg, float* __restrict__ Y, int n) {
    __shared__ __align__(16) float Ws[DIN * DIN];
    __shared__ __align__(16) float Wcs[DIN * 16];
    __shared__ __align__(16) float hbuf[8][DIN];

    int tid  = threadIdx.x;
    int wrp  = tid >> 5;
    int lane = tid & 31;

    for (int i = tid; i < DIN * DIN; i += 256) Ws[i] = Wg[i];
    if constexpr (STAGE == 2)
        for (int i = tid; i < DIN * 16; i += 256) Wcs[i] = Wcg[i];
    __syncthreads();

    int node = blockIdx.x * 8 + wrp;
    if (node >= n) return;

    int half = lane >> 4, fl = lane & 15;
    float invn = g_inv[node];
    int start = g_off[node];
    int cnt   = g_off[node + 1] - start;

    float4 acc = make_float4(0.f, 0.f, 0.f, 0.f);
    for (int base = 0; base < cnt; base += 32) {
        int j = base + lane;
        int2 ev = (j < cnt) ? g_edge[start + j] : make_int2(0, 0);
        int m = cnt - base; if (m > 32) m = 32;
        int steps = (m + 1) >> 1;
        #pragma unroll 4
        for (int k = 0; k < steps; k++) {
            int sel = 2 * k + half;
            int   ss = __shfl_sync(0xffffffffu, ev.x, sel);
            float ww = __int_as_float(__shfl_sync(0xffffffffu, ev.y, sel));
            float4 hv = *(const float4*)&T[(long)ss * DIN + fl * 4];
            acc.x = fmaf(hv.x, ww, acc.x);
            acc.y = fmaf(hv.y, ww, acc.y);
            acc.z = fmaf(hv.z, ww, acc.z);
            acc.w = fmaf(hv.w, ww, acc.w);
        }
    }
    acc.x += __shfl_xor_sync(0xffffffffu, acc.x, 16);
    acc.y += __shfl_xor_sync(0xffffffffu, acc.y, 16);
    acc.z += __shfl_xor_sync(0xffffffffu, acc.z, 16);
    acc.w += __shfl_xor_sync(0xffffffffu, acc.w, 16);

    if (half == 0) {
        float w0 = invn * invn;
        float4 sv = *(const float4*)&T[(long)node * DIN + fl * 4];
        acc.x = fmaf(sv.x, w0, acc.x);
        acc.y = fmaf(sv.y, w0, acc.y);
        acc.z = fmaf(sv.z, w0, acc.z);
        acc.w = fmaf(sv.w, w0, acc.w);
        *(float4*)&hbuf[wrp][fl * 4] = acc;
    }
    __syncwarp();

    // h = relu(aggrow @ W + b); each lane produces 2 output channels.
    float2 bb = ((const float2*)bg)[lane];
    float ox = bb.x, oy = bb.y;
    #pragma unroll
    for (int k = 0; k < DIN; k++) {
        float hk = hbuf[wrp][k];
        float2 wv = *(const float2*)&Ws[k * DIN + 2 * lane];
        ox = fmaf(hk, wv.x, ox);
        oy = fmaf(hk, wv.y, oy);
    }
    ox = fmaxf(ox, 0.0f);
    oy = fmaxf(oy, 0.0f);

    if constexpr (STAGE == 1) {
        ((float2*)Y)[(long)node * 32 + lane] = make_float2(ox, oy);
    } else {
        __syncwarp();
        *(float2*)&hbuf[wrp][2 * lane] = make_float2(ox, oy);
        __syncwarp();
        // classifier: 16 outputs; lane -> out (lane&15), k-half (lane>>4)
        int o = lane & 15;
        int k0 = (lane >> 4) * 32;
        float a2 = 0.f;
        #pragma unroll
        for (int k = 0; k < 32; k++)
            a2 = fmaf(hbuf[wrp][k0 + k], Wcs[(k0 + k) * 16 + o], a2);
        a2 += __shfl_down_sync(0xffffffffu, a2, 16);
        if (lane < 16)
            Y[(long)node * 16 + o] = a2 + bcg[o];
    }
}

// --------------------------------- launch ----------------------------------

extern "C" void kernel_launch(void* const* d_in, const int* in_sizes, int n_in,
                              void* d_out, int out_size) {
    const float* x  = (const float*)d_in[0];
    const int*   ei = (const int*)d_in[1];
    const float* W1 = (const float*)d_in[2];
    const float* b1 = (const float*)d_in[3];
    const float* W2 = (const float*)d_in[4];
    const float* b2 = (const float*)d_in[5];
    const float* Wc = (const float*)d_in[6];
    const float* bc = (const float*)d_in[7];
    float* out = (float*)d_out;

    int n = in_sizes[0] / DIN;       // 50000
    int E = in_sizes[1] / 2;         // 800000

    float* B;
    cudaGetSymbolAddress((void**)&B, g_B);

    int tE = (E + 255) / 256;
    int agrid = (n + 7) / 8;

    count_deg_k<<<tE, 256>>>(ei, E);
    scan_all_k<<<1, 1024>>>(n);
    scatter_k<<<tE, 256>>>(ei, E);
    agg_mm_k<1><<<agrid, 256>>>(x, W1, b1, nullptr, nullptr, B, n);
    agg_mm_k<2><<<agrid, 256>>>(B, W2, b2, Wc, bc, out, n);
}

// round 8
// speedup vs baseline: 1.0161x; 1.0161x over previous
#include <cuda_runtime.h>
#include <cuda_bf16.h>

// ---------------------------------------------------------------------------
// 2-layer GCN + linear classifier, using linearity of the aggregation:
//   Agg(x@W) == Agg(x)@W, so each layer is  h = relu(Agg(t) @ W + b).
//   k1: h1  = relu(Agg(x)  @ W1 + b1)
//   k2: out = relu(Agg(h1) @ W2 + b2) @ Wc + bc
// Agg(t)[n] = t[n]*inv[n]^2 + sum_{e: dst=n} t[src_e]*inv[src_e]*inv[n]
// inv[i] = rsqrt(1 + indeg[i])                (self-loops included)
//
// R7: R6 structure (5 launches, no gemm1, single-block scan) but gather loop
//     reverted to the proven R5 scheme: float2 per lane (1 edge per
//     warp-load = 2 L1 lines), 32-edge smem stash, no SHFL in address path.
// ---------------------------------------------------------------------------

#define MAXN 50176
#define MAXE 1200000
#define DIN 64

__device__ int   g_deg[MAXN];        // statically zero; reset to 0 each run
__device__ float g_inv[MAXN];
__device__ int   g_off[MAXN + 1];
__device__ int   g_cur[MAXN];
__device__ int2  g_edge[MAXE];       // {src, float-bits weight}
__device__ float g_B[MAXN * DIN];

// --------------------------- index width handling --------------------------
// If the edge buffer is int64 (values < 2^31), every odd 32-bit word is 0.
// Each warp detects this locally from the first 256 words (deterministic).

__device__ __forceinline__ int detect64(const int* __restrict__ w) {
    int lane = threadIdx.x & 31;
    int bad = 0;
    #pragma unroll
    for (int j = 0; j < 4; j++)
        if (w[1 + 2 * (lane * 4 + j)] != 0) bad = 1;
    return (__ballot_sync(0xffffffffu, bad) == 0u);
}

__device__ __forceinline__ int load_idx(const int* p, long i, int is64) {
    if (is64) return (int)((const long long*)p)[i];
    return p[i];
}

// ------------------------------- CSR build ---------------------------------

__global__ void count_deg_k(const int* __restrict__ ei, int E) {
    int is64 = detect64(ei);
    int e = blockIdx.x * blockDim.x + threadIdx.x;
    if (e >= E) return;
    int d = load_idx(ei, (long)E + e, is64);
    atomicAdd(&g_deg[d], 1);
}

// Single block does the whole exclusive scan: offsets[n+1], inv, cur,
// and resets g_deg to zero so the next graph replay starts clean.
__global__ __launch_bounds__(1024) void scan_all_k(int n) {
    __shared__ int s[1024];
    const int C = (n + 1023) >> 10;          // elems per thread
    int t = threadIdx.x;
    int i0 = t * C;
    int i1 = i0 + C; if (i1 > n) i1 = n;

    int sum = 0;
    for (int i = i0; i < i1; i++) {
        int c = g_deg[i];
        g_inv[i] = rsqrtf((float)(c + 1));
        sum += c;
    }
    s[t] = sum;
    __syncthreads();
    #pragma unroll
    for (int d = 1; d < 1024; d <<= 1) {
        int v = (t >= d) ? s[t - d] : 0;
        __syncthreads();
        s[t] += v;
        __syncthreads();
    }
    int run = s[t] - sum;                    // exclusive prefix
    for (int i = i0; i < i1; i++) {
        int c = g_deg[i];
        g_off[i] = run;
        g_cur[i] = run;
        run += c;
        g_deg[i] = 0;                        // reset for next replay
    }
    if (t == 1023) g_off[n] = s[1023];
}

__global__ void scatter_k(const int* __restrict__ ei, int E) {
    int is64 = detect64(ei);
    int e = blockIdx.x * blockDim.x + threadIdx.x;
    if (e >= E) return;
    int sN = load_idx(ei, e, is64);
    int d  = load_idx(ei, (long)E + e, is64);
    int pos = atomicAdd(&g_cur[d], 1);
    g_edge[pos] = make_int2(sN, __float_as_int(g_inv[sN] * g_inv[d]));
}

// ---------------------- aggregation + fused transform -----------------------
// One warp per node; lane owns feature channels {2*lane, 2*lane+1} (float2),
// so each edge gather is exactly one 256B warp-load (2 L1 lines). Edges for
// the chunk are stashed in smem and broadcast via conflict-free LDS.
// Epilogue: h = relu(Agg_row @ W + b); STAGE 2 additionally applies the
// 64x16 classifier and writes 16 outputs.

template <int STAGE>
__global__ __launch_bounds__(256) void agg_mm_k(
    const float* __restrict__ T, const float* __restrict__ Wg,
    const float* __restrict__ bg, const float* __restrict__ Wcg,
    const float* __restrict__ bcg, float* __restrict__ Y, int n) {
    __shared__ __align__(16) float Ws[DIN * DIN];
    __shared__ __align__(16) float Wcs[DIN * 16];
    __shared__ __align__(16) float hbuf[8][DIN];
    __shared__ __align__(16) int2  ebuf[8][32];

    int tid  = threadIdx.x;
    int wrp  = tid >> 5;
    int lane = tid & 31;

    for (int i = tid; i < DIN * DIN; i += 256) Ws[i] = Wg[i];
    if constexpr (STAGE == 2)
        for (int i = tid; i < DIN * 16; i += 256) Wcs[i] = Wcg[i];
    __syncthreads();

    int node = blockIdx.x * 8 + wrp;
    if (node >= n) return;

    const float2* Tv = (const float2*)T;
    float invn = g_inv[node];
    float w0 = invn * invn;
    float2 sv = Tv[(long)node * 32 + lane];
    float accx = sv.x * w0, accy = sv.y * w0;

    int start = g_off[node];
    int cnt   = g_off[node + 1] - start;

    for (int base = 0; base < cnt; base += 32) {
        int j = base + lane;
        if (j < cnt) ebuf[wrp][lane] = g_edge[start + j];
        __syncwarp();
        int m = cnt - base; if (m > 32) m = 32;
        #pragma unroll 4
        for (int k = 0; k < m; k++) {
            int2 e = ebuf[wrp][k];
            float ww = __int_as_float(e.y);
            float2 hv = Tv[(long)e.x * 32 + lane];
            accx = fmaf(hv.x, ww, accx);
            accy = fmaf(hv.y, ww, accy);
        }
        __syncwarp();
    }

    // stash aggregated row for the warp-cooperative matmul
    *(float2*)&hbuf[wrp][2 * lane] = make_float2(accx, accy);
    __syncwarp();

    // h = relu(aggrow @ W + b); each lane produces 2 output channels.
    float2 bb = ((const float2*)bg)[lane];
    float ox = bb.x, oy = bb.y;
    #pragma unroll
    for (int k = 0; k < DIN; k++) {
        float hk = hbuf[wrp][k];
        float2 wv = *(const float2*)&Ws[k * DIN + 2 * lane];
        ox = fmaf(hk, wv.x, ox);
        oy = fmaf(hk, wv.y, oy);
    }
    ox = fmaxf(ox, 0.0f);
    oy = fmaxf(oy, 0.0f);

    if constexpr (STAGE == 1) {
        ((float2*)Y)[(long)node * 32 + lane] = make_float2(ox, oy);
    } else {
        __syncwarp();
        *(float2*)&hbuf[wrp][2 * lane] = make_float2(ox, oy);
        __syncwarp();
        // classifier: 16 outputs; lane -> out (lane&15), k-half (lane>>4)
        int o = lane & 15;
        int k0 = (lane >> 4) * 32;
        float a2 = 0.f;
        #pragma unroll
        for (int k = 0; k < 32; k++)
            a2 = fmaf(hbuf[wrp][k0 + k], Wcs[(k0 + k) * 16 + o], a2);
        a2 += __shfl_down_sync(0xffffffffu, a2, 16);
        if (lane < 16)
            Y[(long)node * 16 + o] = a2 + bcg[o];
    }
}

// --------------------------------- launch ----------------------------------

extern "C" void kernel_launch(void* const* d_in, const int* in_sizes, int n_in,
                              void* d_out, int out_size) {
    const float* x  = (const float*)d_in[0];
    const int*   ei = (const int*)d_in[1];
    const float* W1 = (const float*)d_in[2];
    const float* b1 = (const float*)d_in[3];
    const float* W2 = (const float*)d_in[4];
    const float* b2 = (const float*)d_in[5];
    const float* Wc = (const float*)d_in[6];
    const float* bc = (const float*)d_in[7];
    float* out = (float*)d_out;

    int n = in_sizes[0] / DIN;       // 50000
    int E = in_sizes[1] / 2;         // 800000

    float* B;
    cudaGetSymbolAddress((void**)&B, g_B);

    int tE = (E + 255) / 256;
    int agrid = (n + 7) / 8;

    count_deg_k<<<tE, 256>>>(ei, E);
    scan_all_k<<<1, 1024>>>(n);
    scatter_k<<<tE, 256>>>(ei, E);
    agg_mm_k<1><<<agrid, 256>>>(x, W1, b1, nullptr, nullptr, B, n);
    agg_mm_k<2><<<agrid, 256>>>(B, W2, b2, Wc, bc, out, n);
}

// round 10
// speedup vs baseline: 1.7967x; 1.7682x over previous
#include <cuda_runtime.h>
#include <cuda_bf16.h>

// ---------------------------------------------------------------------------
// 2-layer GCN + linear classifier, using linearity of the aggregation:
//   Agg(x@W) == Agg(x)@W, so each layer is  h = relu(Agg(t) @ W + b).
//   k1: h1  = relu(Agg(x)  @ W1 + b1)
//   k2: out = relu(Agg(h1) @ W2 + b2) @ Wc + bc
// Agg(t)[n] = t[n]*inv[n]^2 + sum_{e: dst=n} t[src_e]*inv[src_e]*inv[n]
//
// R8: scan_all_k (single-block, uncoalesced, ~130us!) replaced by the proven
//     coalesced 3-kernel scan; epilogue matmul vectorized (float4 W, k-split
//     across half-warps). 7 launches.
// ---------------------------------------------------------------------------

#define MAXN 50176
#define MAXE 1200000
#define DIN 64

__device__ int   g_deg[MAXN];        // statically zero; reset in scan3 each run
__device__ float g_inv[MAXN];
__device__ int   g_off[MAXN + 1];
__device__ int   g_cur[MAXN];
__device__ int   g_bsum[256];
__device__ int2  g_edge[MAXE];       // {src, float-bits weight}
__device__ float g_B[MAXN * DIN];

// --------------------------- index width handling --------------------------
// If the edge buffer is int64 (values < 2^31), every odd 32-bit word is 0.

__device__ __forceinline__ int detect64(const int* __restrict__ w) {
    int lane = threadIdx.x & 31;
    int bad = 0;
    #pragma unroll
    for (int j = 0; j < 4; j++)
        if (w[1 + 2 * (lane * 4 + j)] != 0) bad = 1;
    return (__ballot_sync(0xffffffffu, bad) == 0u);
}

__device__ __forceinline__ int load_idx(const int* p, long i, int is64) {
    if (is64) return (int)((const long long*)p)[i];
    return p[i];
}

// ------------------------------- CSR build ---------------------------------

__global__ void count_deg_k(const int* __restrict__ ei, int E) {
    int is64 = detect64(ei);
    int e = blockIdx.x * blockDim.x + threadIdx.x;
    if (e >= E) return;
    int d = load_idx(ei, (long)E + e, is64);
    atomicAdd(&g_deg[d], 1);
}

// coalesced block-local inclusive scan of deg; also finalizes g_inv.
__global__ __launch_bounds__(1024) void scan1_k(int n) {
    __shared__ int s[1024];
    int i = blockIdx.x * 1024 + threadIdx.x;
    int v = (i < n) ? g_deg[i] : 0;
    if (i < n) g_inv[i] = rsqrtf((float)(v + 1));
    s[threadIdx.x] = v;
    __syncthreads();
    #pragma unroll
    for (int d = 1; d < 1024; d <<= 1) {
        int t = (threadIdx.x >= d) ? s[threadIdx.x - d] : 0;
        __syncthreads();
        s[threadIdx.x] += t;
        __syncthreads();
    }
    if (i < n) g_off[i] = s[threadIdx.x];        // inclusive (temp)
    if (threadIdx.x == 1023) g_bsum[blockIdx.x] = s[1023];
}

// warp-parallel exclusive scan of up to 64 block sums (nb = 49 here).
__global__ void scan2_k(int nb) {
    int lane = threadIdx.x;
    int v0 = (lane < nb)      ? g_bsum[lane]      : 0;
    int v1 = (lane + 32 < nb) ? g_bsum[lane + 32] : 0;
    int s0 = v0, s1 = v1;
    #pragma unroll
    for (int d = 1; d < 32; d <<= 1) {
        int t0 = __shfl_up_sync(0xffffffffu, s0, d);
        int t1 = __shfl_up_sync(0xffffffffu, s1, d);
        if (lane >= d) { s0 += t0; s1 += t1; }
    }
    int tot0 = __shfl_sync(0xffffffffu, s0, 31);
    s1 += tot0;
    if (lane < nb)      g_bsum[lane]      = s0 - v0;
    if (lane + 32 < nb) g_bsum[lane + 32] = s1 - v1;
}

// finalize exclusive offsets, init cur, reset deg for next graph replay.
__global__ __launch_bounds__(1024) void scan3_k(int n, int E) {
    int i = blockIdx.x * 1024 + threadIdx.x;
    if (i == 0) g_off[n] = E;
    if (i >= n) return;
    int c = g_deg[i];
    int excl = g_off[i] - c + g_bsum[blockIdx.x];
    g_off[i] = excl;
    g_cur[i] = excl;
    g_deg[i] = 0;
}

__global__ void scatter_k(const int* __restrict__ ei, int E) {
    int is64 = detect64(ei);
    int e = blockIdx.x * blockDim.x + threadIdx.x;
    if (e >= E) return;
    int sN = load_idx(ei, e, is64);
    int d  = load_idx(ei, (long)E + e, is64);
    int pos = atomicAdd(&g_cur[d], 1);
    g_edge[pos] = make_int2(sN, __float_as_int(g_inv[sN] * g_inv[d]));
}

// ---------------------- aggregation + fused transform -----------------------
// One warp per node; lane owns feature channels {2*lane, 2*lane+1} (float2)
// for the gather (1 edge per warp-load, 32-edge smem stash broadcast).
// Epilogue mm: lane -> 4 consecutive outputs (float4 W), half-warps split k
// (k in [32*(lane>>4), +32)), 4 shfl_xor to combine. STAGE 2 adds the 64x16
// classifier.

template <int STAGE>
__global__ __launch_bounds__(256) void agg_mm_k(
    const float* __restrict__ T, const float* __restrict__ Wg,
    const float* __restrict__ bg, const float* __restrict__ Wcg,
    const float* __restrict__ bcg, float* __restrict__ Y, int n) {
    __shared__ __align__(16) float Ws[DIN * DIN];
    __shared__ __align__(16) float Wcs[DIN * 16];
    __shared__ __align__(16) float hbuf[8][DIN];
    __shared__ __align__(16) int2  ebuf[8][32];

    int tid  = threadIdx.x;
    int wrp  = tid >> 5;
    int lane = tid & 31;

    for (int i = tid; i < DIN * DIN; i += 256) Ws[i] = Wg[i];
    if constexpr (STAGE == 2)
        for (int i = tid; i < DIN * 16; i += 256) Wcs[i] = Wcg[i];
    __syncthreads();

    int node = blockIdx.x * 8 + wrp;
    if (node >= n) return;

    const float2* Tv = (const float2*)T;
    float invn = g_inv[node];
    float w0 = invn * invn;
    float2 sv = Tv[(long)node * 32 + lane];
    float accx = sv.x * w0, accy = sv.y * w0;

    int start = g_off[node];
    int cnt   = g_off[node + 1] - start;

    for (int base = 0; base < cnt; base += 32) {
        int j = base + lane;
        if (j < cnt) ebuf[wrp][lane] = g_edge[start + j];
        __syncwarp();
        int m = cnt - base; if (m > 32) m = 32;
        #pragma unroll 4
        for (int k = 0; k < m; k++) {
            int2 e = ebuf[wrp][k];
            float ww = __int_as_float(e.y);
            float2 hv = Tv[(long)e.x * 32 + lane];
            accx = fmaf(hv.x, ww, accx);
            accy = fmaf(hv.y, ww, accy);
        }
        __syncwarp();
    }

    // stash aggregated row for the warp-cooperative matmul
    *(float2*)&hbuf[wrp][2 * lane] = make_float2(accx, accy);
    __syncwarp();

    // h = relu(aggrow @ W + b): lane -> outputs [o4, o4+4), k split by half.
    int o4 = (lane & 15) * 4;
    int kb = (lane >> 4) * 32;
    float4 a = make_float4(0.f, 0.f, 0.f, 0.f);
    #pragma unroll
    for (int k = 0; k < 32; k++) {
        float hk = hbuf[wrp][kb + k];
        float4 w = *(const float4*)&Ws[(kb + k) * DIN + o4];
        a.x = fmaf(hk, w.x, a.x);
        a.y = fmaf(hk, w.y, a.y);
        a.z = fmaf(hk, w.z, a.z);
        a.w = fmaf(hk, w.w, a.w);
    }
    a.x += __shfl_xor_sync(0xffffffffu, a.x, 16);
    a.y += __shfl_xor_sync(0xffffffffu, a.y, 16);
    a.z += __shfl_xor_sync(0xffffffffu, a.z, 16);
    a.w += __shfl_xor_sync(0xffffffffu, a.w, 16);

    float4 bb = *(const float4*)&bg[o4];
    a.x = fmaxf(a.x + bb.x, 0.0f);
    a.y = fmaxf(a.y + bb.y, 0.0f);
    a.z = fmaxf(a.z + bb.z, 0.0f);
    a.w = fmaxf(a.w + bb.w, 0.0f);

    if constexpr (STAGE == 1) {
        if (lane < 16)
            *(float4*)&Y[(long)node * DIN + o4] = a;
    } else {
        __syncwarp();
        if (lane < 16) *(float4*)&hbuf[wrp][o4] = a;
        __syncwarp();
        // classifier: 16 outputs; lane -> out (lane&15), k-half (lane>>4)
        int o = lane & 15;
        int k0 = (lane >> 4) * 32;
        float a2 = 0.f;
        #pragma unroll
        for (int k = 0; k < 32; k++)
            a2 = fmaf(hbuf[wrp][k0 + k], Wcs[(k0 + k) * 16 + o], a2);
        a2 += __shfl_down_sync(0xffffffffu, a2, 16);
        if (lane < 16)
            Y[(long)node * 16 + o] = a2 + bcg[o];
    }
}

// --------------------------------- launch ----------------------------------

extern "C" void kernel_launch(void* const* d_in, const int* in_sizes, int n_in,
                              void* d_out, int out_size) {
    const float* x  = (const float*)d_in[0];
    const int*   ei = (const int*)d_in[1];
    const float* W1 = (const float*)d_in[2];
    const float* b1 = (const float*)d_in[3];
    const float* W2 = (const float*)d_in[4];
    const float* b2 = (const float*)d_in[5];
    const float* Wc = (const float*)d_in[6];
    const float* bc = (const float*)d_in[7];
    float* out = (float*)d_out;

    int n = in_sizes[0] / DIN;       // 50000
    int E = in_sizes[1] / 2;         // 800000

    float* B;
    cudaGetSymbolAddress((void**)&B, g_B);

    int tE = (E + 255) / 256;
    int nb = (n + 1023) / 1024;
    int agrid = (n + 7) / 8;

    count_deg_k<<<tE, 256>>>(ei, E);
    scan1_k<<<nb, 1024>>>(n);
    scan2_k<<<1, 32>>>(nb);
    scan3_k<<<nb, 1024>>>(n, E);
    scatter_k<<<tE, 256>>>(ei, E);
    agg_mm_k<1><<<agrid, 256>>>(x, W1, b1, nullptr, nullptr, B, n);
    agg_mm_k<2><<<agrid, 256>>>(B, W2, b2, Wc, bc, out, n);
}